// round 3
// baseline (speedup 1.0000x reference)
#include <cuda_runtime.h>
#include <cstdint>

// ---------------- problem constants ----------------
#define Bb      16
#define Ll      2048
#define DMODEL  256
#define DINNER  512
#define DSTATE  32
#define DCONV   4
#define DTRANK  16
#define HMLP    32
#define BINS    256
#define ML      (Bb*Ll)            // 32768 rows

__device__ __forceinline__ float fast_exp2(float x) {
    float r;
    asm("ex2.approx.ftz.f32 %0, %1;" : "=f"(r) : "f"(x));
    return r;
}

// ---------------- scratch (static device arrays; no allocation) ----------------
__device__ float  sXC  [(size_t)ML * DINNER];        // conv input (first half of xz)
__device__ float  sZ   [(size_t)ML * DINNER];        // gate z (second half of xz)
__device__ float  sU   [(size_t)ML * DINNER];        // silu(conv) contiguous for GEMM
__device__ float2 sDU  [(size_t)ML * DINNER];        // {dt, u} packed for scan
__device__ float  sDTLO[(size_t)ML * DTRANK];        // dt low-rank
__device__ float2 sBC  [(size_t)ML * DSTATE];        // {B, C} interleaved for scan
__device__ float  sY   [(size_t)ML * DINNER];        // gated scan output
__device__ float  sM   [(size_t)ML * DMODEL];        // mamba output
__device__ float  sH   [(size_t)ML * HMLP];          // mlp hidden

// ---------------- generic fp32 SGEMM: C[m,n] = sum_k A[m,k]*W[n,k] ----------------
// M must be multiple of 128; K multiple of 16; N arbitrary (guarded).
#define BM 128
#define BN 64
#define BKK 16

// epilogue modes
#define EPI_PLAIN   0
#define EPI_SPLITXZ 1   // n<512 -> aux0 (xc), else aux1 (z)
#define EPI_DBC     2   // n<16 -> C(dtlo); 16..47 -> aux0 as float2 .x; 48..79 -> .y
#define EPI_LEAKY   3   // +bias, leaky_relu(0.01)
#define EPI_SIGMOID 4   // +bias, sigmoid

template<int E>
__global__ __launch_bounds__(256)
void sgemm_k(const float* __restrict__ A, const float* __restrict__ W,
             const float* __restrict__ bias, float* __restrict__ C,
             int M, int N, int K, float* __restrict__ aux0, float* __restrict__ aux1)
{
    __shared__ float As[BKK][BM];
    __shared__ float Ws[BKK][BN];

    const int tid = threadIdx.x;
    const int tx  = tid & 15;
    const int ty  = tid >> 4;
    const int m0  = blockIdx.y * BM;
    const int n0  = blockIdx.x * BN;

    float acc[8][4];
    #pragma unroll
    for (int i = 0; i < 8; ++i)
        #pragma unroll
        for (int j = 0; j < 4; ++j) acc[i][j] = 0.f;

    for (int k0 = 0; k0 < K; k0 += BKK) {
        // load A tile: 128 rows x 16k = 512 float4; 2 per thread
        #pragma unroll
        for (int r = 0; r < 2; ++r) {
            int j   = tid + 256 * r;
            int row = j >> 2;
            int kq  = j & 3;
            float4 v = *(const float4*)(A + (size_t)(m0 + row) * K + k0 + kq * 4);
            As[kq*4+0][row] = v.x;
            As[kq*4+1][row] = v.y;
            As[kq*4+2][row] = v.z;
            As[kq*4+3][row] = v.w;
        }
        // load W tile: 64 rows x 16k = 256 float4; 1 per thread (guard n)
        {
            int row = tid >> 2;
            int kq  = tid & 3;
            float4 v = make_float4(0.f, 0.f, 0.f, 0.f);
            if (n0 + row < N)
                v = *(const float4*)(W + (size_t)(n0 + row) * K + k0 + kq * 4);
            Ws[kq*4+0][row] = v.x;
            Ws[kq*4+1][row] = v.y;
            Ws[kq*4+2][row] = v.z;
            Ws[kq*4+3][row] = v.w;
        }
        __syncthreads();

        #pragma unroll
        for (int kk = 0; kk < BKK; ++kk) {
            float4 a0 = *(const float4*)&As[kk][ty * 8];
            float4 a1 = *(const float4*)&As[kk][ty * 8 + 4];
            float4 wv = *(const float4*)&Ws[kk][tx * 4];
            float a[8] = {a0.x, a0.y, a0.z, a0.w, a1.x, a1.y, a1.z, a1.w};
            float w[4] = {wv.x, wv.y, wv.z, wv.w};
            #pragma unroll
            for (int i = 0; i < 8; ++i)
                #pragma unroll
                for (int j = 0; j < 4; ++j)
                    acc[i][j] = fmaf(a[i], w[j], acc[i][j]);
        }
        __syncthreads();
    }

    // store with epilogue
    #pragma unroll
    for (int i = 0; i < 8; ++i) {
        int m = m0 + ty * 8 + i;
        #pragma unroll
        for (int j = 0; j < 4; ++j) {
            int n = n0 + tx * 4 + j;
            if (n >= N) continue;
            float v = acc[i][j];
            if (E == EPI_PLAIN) {
                C[(size_t)m * N + n] = v;
            } else if (E == EPI_SPLITXZ) {
                if (n < DINNER) aux0[(size_t)m * DINNER + n] = v;
                else            aux1[(size_t)m * DINNER + (n - DINNER)] = v;
            } else if (E == EPI_DBC) {
                if (n < DTRANK)               C[(size_t)m * DTRANK + n] = v;
                else if (n < DTRANK + DSTATE) aux0[((size_t)m * DSTATE + (n - DTRANK)) * 2 + 0] = v;
                else                          aux0[((size_t)m * DSTATE + (n - DTRANK - DSTATE)) * 2 + 1] = v;
            } else if (E == EPI_LEAKY) {
                v += bias[n];
                v = (v > 0.f) ? v : 0.01f * v;
                C[(size_t)m * N + n] = v;
            } else if (E == EPI_SIGMOID) {
                v += bias[n];
                v = 1.f / (1.f + __expf(-v));
                C[(size_t)m * N + n] = v;
            }
        }
    }
}

// ---------------- depthwise causal conv + SiLU ----------------
__global__ __launch_bounds__(256)
void conv_silu_k(const float* __restrict__ cw, const float* __restrict__ cb)
{
    int idx = blockIdx.x * blockDim.x + threadIdx.x;     // < ML*DINNER
    int e   = idx & (DINNER - 1);
    int bl  = idx >> 9;
    int l   = bl & (Ll - 1);

    float acc = cb[e];
    #pragma unroll
    for (int k = 0; k < DCONV; ++k) {
        int ll = l - (DCONV - 1) + k;
        if (ll >= 0)
            acc = fmaf(sXC[(size_t)(bl - (DCONV - 1) + k) * DINNER + e], cw[e * DCONV + k], acc);
    }
    float u = acc / (1.f + __expf(-acc));   // silu
    sU[idx] = u;
    sDU[idx].y = u;
}

// ---------------- dt projection + softplus ----------------
__global__ __launch_bounds__(512)
void dt_k(const float* __restrict__ Wdt, const float* __restrict__ bdt)
{
    int row = blockIdx.x;       // 0..ML-1
    int d   = threadIdx.x;      // 0..511
    __shared__ float lo[DTRANK];
    if (d < DTRANK) lo[d] = sDTLO[(size_t)row * DTRANK + d];
    __syncthreads();

    const float4* w = (const float4*)(Wdt + d * DTRANK);
    float4 w0 = w[0], w1 = w[1], w2 = w[2], w3 = w[3];
    float acc = bdt[d];
    acc = fmaf(lo[0],  w0.x, acc); acc = fmaf(lo[1],  w0.y, acc);
    acc = fmaf(lo[2],  w0.z, acc); acc = fmaf(lo[3],  w0.w, acc);
    acc = fmaf(lo[4],  w1.x, acc); acc = fmaf(lo[5],  w1.y, acc);
    acc = fmaf(lo[6],  w1.z, acc); acc = fmaf(lo[7],  w1.w, acc);
    acc = fmaf(lo[8],  w2.x, acc); acc = fmaf(lo[9],  w2.y, acc);
    acc = fmaf(lo[10], w2.z, acc); acc = fmaf(lo[11], w2.w, acc);
    acc = fmaf(lo[12], w3.x, acc); acc = fmaf(lo[13], w3.y, acc);
    acc = fmaf(lo[14], w3.z, acc); acc = fmaf(lo[15], w3.w, acc);

    float sp = (acc > 20.f) ? acc : log1pf(__expf(acc));
    sDU[(size_t)row * DINNER + d].x = sp;
}

// ---------------- selective scan (warp per (b,d), lane = state) ----------------
__global__ __launch_bounds__(256)
void scan_k(const float* __restrict__ A_log, const float* __restrict__ Dp)
{
    const int b = blockIdx.y;
    const int d = blockIdx.x * 8 + (threadIdx.x >> 5);
    const int s = threadIdx.x & 31;

    // A2 = -exp(A_log) * log2(e), so exp(dt*A) = exp2(dt * A2)
    const float A2 = -__expf(A_log[d * DSTATE + s]) * 1.4426950408889634f;
    const float Dd = Dp[d];

    const float2* __restrict__ du = sDU + (size_t)b * Ll * DINNER + d;
    const float2* __restrict__ bc = sBC + (size_t)b * Ll * DSTATE + s;
    const float*  __restrict__ zp = sZ  + (size_t)b * Ll * DINNER + d;
    float*        __restrict__ yp = sY  + (size_t)b * Ll * DINNER + d;

    float h = 0.f;
    #pragma unroll 4
    for (int l = 0; l < Ll; ++l) {
        float2 duv = du[(size_t)l * DINNER];   // uniform across warp
        float2 bcv = bc[(size_t)l * DSTATE];   // per-lane {B, C}
        float  zv  = zp[(size_t)l * DINNER];   // uniform

        float e   = fast_exp2(duv.x * A2);
        float dtu = duv.x * duv.y;
        h = fmaf(h, e, dtu * bcv.x);
        float y = h * bcv.y;

        // warp butterfly reduction over 32 states
        y += __shfl_xor_sync(0xffffffffu, y, 16);
        y += __shfl_xor_sync(0xffffffffu, y, 8);
        y += __shfl_xor_sync(0xffffffffu, y, 4);
        y += __shfl_xor_sync(0xffffffffu, y, 2);
        y += __shfl_xor_sync(0xffffffffu, y, 1);

        if (s == 0) {
            y = fmaf(duv.y, Dd, y);
            float sg = 1.f / (1.f + __expf(-zv));
            yp[(size_t)l * DINNER] = y * (zv * sg);   // gate with silu(z)
        }
    }
}

// ---------------- launch ----------------
extern "C" void kernel_launch(void* const* d_in, const int* in_sizes, int n_in,
                              void* d_out, int out_size)
{
    const float* x      = (const float*)d_in[0];
    const float* W_in   = (const float*)d_in[1];
    const float* conv_w = (const float*)d_in[2];
    const float* conv_b = (const float*)d_in[3];
    const float* W_xprj = (const float*)d_in[4];
    const float* W_dt   = (const float*)d_in[5];
    const float* b_dt   = (const float*)d_in[6];
    const float* A_log  = (const float*)d_in[7];
    const float* Dvec   = (const float*)d_in[8];
    const float* W_out  = (const float*)d_in[9];
    const float* W_ff1  = (const float*)d_in[10];
    const float* b_ff1  = (const float*)d_in[11];
    const float* W_ff2  = (const float*)d_in[12];
    const float* b_ff2  = (const float*)d_in[13];
    float* out = (float*)d_out;

    float *pXC, *pZ, *pU, *pDTLO, *pY, *pM, *pH;
    float2 *pDU, *pBC;
    cudaGetSymbolAddress((void**)&pXC,   sXC);
    cudaGetSymbolAddress((void**)&pZ,    sZ);
    cudaGetSymbolAddress((void**)&pU,    sU);
    cudaGetSymbolAddress((void**)&pDU,   sDU);
    cudaGetSymbolAddress((void**)&pDTLO, sDTLO);
    cudaGetSymbolAddress((void**)&pBC,   sBC);
    cudaGetSymbolAddress((void**)&pY,    sY);
    cudaGetSymbolAddress((void**)&pM,    sM);
    cudaGetSymbolAddress((void**)&pH,    sH);

    const int mtiles = ML / BM;   // 256

    // 1) xz = x @ W_in^T  -> split into xc / z
    {
        dim3 g((2 * DINNER + BN - 1) / BN, mtiles);
        sgemm_k<EPI_SPLITXZ><<<g, 256>>>(x, W_in, nullptr, nullptr,
                                         ML, 2 * DINNER, DMODEL, pXC, pZ);
    }
    // 2) depthwise conv + silu -> u
    {
        int n = ML * DINNER;
        conv_silu_k<<<n / 256, 256>>>(conv_w, conv_b);
    }
    // 3) dbc = u @ W_xproj^T -> scatter dtlo / {B,C}
    {
        dim3 g((DTRANK + 2 * DSTATE + BN - 1) / BN, mtiles);
        sgemm_k<EPI_DBC><<<g, 256>>>(pU, W_xprj, nullptr, pDTLO,
                                     ML, DTRANK + 2 * DSTATE, DINNER, (float*)pBC, nullptr);
    }
    // 4) dt = softplus(dtlo @ W_dt^T + b_dt)
    dt_k<<<ML, DINNER>>>(W_dt, b_dt);

    // 5) selective scan (+D skip, silu(z) gate)
    {
        dim3 g(DINNER / 8, Bb);
        scan_k<<<g, 256>>>(A_log, Dvec);
    }
    // 6) m = y @ W_out^T
    {
        dim3 g((DMODEL + BN - 1) / BN, mtiles);
        sgemm_k<EPI_PLAIN><<<g, 256>>>(pY, W_out, nullptr, pM,
                                       ML, DMODEL, DINNER, nullptr, nullptr);
    }
    // 7) h = leaky_relu(m @ W_ff1^T + b_ff1)
    {
        dim3 g((HMLP + BN - 1) / BN, mtiles);
        sgemm_k<EPI_LEAKY><<<g, 256>>>(pM, W_ff1, b_ff1, pH,
                                       ML, HMLP, DMODEL, nullptr, nullptr);
    }
    // 8) out = sigmoid(h @ W_ff2^T + b_ff2)
    {
        dim3 g((BINS + BN - 1) / BN, mtiles);
        sgemm_k<EPI_SIGMOID><<<g, 256>>>(pH, W_ff2, b_ff2, out,
                                         ML, BINS, HMLP, nullptr, nullptr);
    }
}